// round 6
// baseline (speedup 1.0000x reference)
#include <cuda_runtime.h>
#include <cstdint>

// Problem constants
#define BATCH      32768
#define NFEAT      128
#define NTREES     4000
#define NINT       63
#define NLEAF      64
#define NCLS       10
#define TREE_DEPTH 6
#define LR         0.1f

// Tiling: one CTA per SM, balanced grid
#define TPB        224                        // 7 warps = 224 samples per CTA
#define GRID       ((BATCH + TPB - 1) / TPB)  // 147 CTAs over 148 SMs

#define CHUNK_STAGES 4
#define CHUNK_TREES  (CHUNK_STAGES * NCLS)    // 40 trees per buffer
#define NCHUNK       (NTREES / CHUNK_TREES)   // 100

// Fused node: int2 { f * (TPB*4) byte offset, threshold bits }
#define NODE_I2S    (CHUNK_TREES * NINT)      // 2520 int2 per chunk
#define NODE_BYTES  (NODE_I2S * 8)            // 20160 (16B multiple)
#define LEAF_WORDS  (CHUNK_TREES * NLEAF)     // 2560
#define LEAF_BYTES  (LEAF_WORDS * 4)          // 10240
#define BUF_BYTES   (NODE_BYTES + LEAF_BYTES) // 30400

// x tile: FEATURE-MAJOR, xs[f * TPB + r]; 224 ≡ 0 (mod 32) -> gather bank = lane.
#define XS_BYTES    (NFEAT * TPB * 4)         // 114688
#define NODE_OFF    XS_BYTES
#define LEAF_OFF(b) (XS_BYTES + 2 * NODE_BYTES + (b) * LEAF_BYTES)
#define MBAR_OFF    (XS_BYTES + 2 * NODE_BYTES + 2 * LEAF_BYTES)
#define SMEM_TOTAL  (MBAR_OFF + 16)           // 175520

// One-time fused/prescaled node table in device-global scratch (allowed).
__device__ int2 g_nodes[NTREES * NINT];

extern __shared__ char smem_raw[];

__device__ __forceinline__ uint32_t s2u(const void* p) {
    uint32_t a;
    asm("{ .reg .u64 t; cvta.to.shared.u64 t, %1; cvt.u32.u64 %0, t; }"
        : "=r"(a) : "l"(p));
    return a;
}

__device__ __forceinline__ void mbar_init(uint32_t bar, uint32_t cnt) {
    asm volatile("mbarrier.init.shared.b64 [%0], %1;" :: "r"(bar), "r"(cnt) : "memory");
}

__device__ __forceinline__ void mbar_expect_tx(uint32_t bar, uint32_t bytes) {
    asm volatile("mbarrier.arrive.expect_tx.shared.b64 _, [%0], %1;"
                 :: "r"(bar), "r"(bytes) : "memory");
}

__device__ __forceinline__ void mbar_wait(uint32_t bar, uint32_t parity) {
    uint32_t done;
    asm volatile(
        "{\n\t.reg .pred p;\n\t"
        "mbarrier.try_wait.parity.acquire.cta.shared::cta.b64 p, [%1], %2;\n\t"
        "selp.b32 %0, 1, 0, p;\n\t}"
        : "=r"(done) : "r"(bar), "r"(parity) : "memory");
    while (!done) {
        asm volatile(
            "{\n\t.reg .pred p;\n\t"
            "mbarrier.try_wait.parity.acquire.cta.shared::cta.b64 p, [%1], %2, 0x989680;\n\t"
            "selp.b32 %0, 1, 0, p;\n\t}"
            : "=r"(done) : "r"(bar), "r"(parity) : "memory");
    }
}

__device__ __forceinline__ void bulk_g2s(uint32_t dst, const void* src,
                                         uint32_t bytes, uint32_t bar) {
    asm volatile(
        "cp.async.bulk.shared::cluster.global.mbarrier::complete_tx::bytes "
        "[%0], [%1], %2, [%3];"
        :: "r"(dst), "l"(src), "r"(bytes), "r"(bar) : "memory");
}

// ---- one-time: fuse {feature, threshold} -> int2 {byte-offset, thr bits} ----
__global__ void prep_nodes_kernel(const int* __restrict__ features,
                                  const float* __restrict__ thresholds)
{
    int i = blockIdx.x * blockDim.x + threadIdx.x;
    if (i < NTREES * NINT) {
        g_nodes[i] = make_int2(features[i] * (TPB * 4),
                               __float_as_int(thresholds[i]));
    }
}

__global__ void __launch_bounds__(TPB, 1)
gbt_forest_kernel(const float* __restrict__ x,
                  const float* __restrict__ leaf_values,
                  const float* __restrict__ init_out,
                  float*       __restrict__ out)
{
    float* xs = reinterpret_cast<float*>(smem_raw);
    uint64_t* mbar = reinterpret_cast<uint64_t*>(smem_raw + MBAR_OFF);

    const int tid  = threadIdx.x;
    const int lane = tid & 31;
    const int warp = tid >> 5;
    const int base = blockIdx.x * TPB;
    const int rows = min(TPB, BATCH - base);

    const uint32_t bar0 = s2u(&mbar[0]);
    const uint32_t bar1 = s2u(&mbar[1]);
    const uint32_t nodeDst0 = s2u(smem_raw + NODE_OFF);
    const uint32_t nodeDst1 = s2u(smem_raw + NODE_OFF + NODE_BYTES);
    const uint32_t leafDst0 = s2u(smem_raw + LEAF_OFF(0));
    const uint32_t leafDst1 = s2u(smem_raw + LEAF_OFF(1));

    const int2* g_nodes_p = g_nodes;   // device-global fused table

    // --- init barriers + prefetch chunks 0,1 ---
    if (tid == 0) {
        mbar_init(bar0, 1);
        mbar_init(bar1, 1);
        asm volatile("fence.proxy.async.shared::cta;" ::: "memory");
        mbar_expect_tx(bar0, BUF_BYTES);
        bulk_g2s(nodeDst0, g_nodes_p,               NODE_BYTES, bar0);
        bulk_g2s(leafDst0, leaf_values,             LEAF_BYTES, bar0);
        mbar_expect_tx(bar1, BUF_BYTES);
        bulk_g2s(nodeDst1, g_nodes_p + NODE_I2S,    NODE_BYTES, bar1);
        bulk_g2s(leafDst1, leaf_values + LEAF_WORDS, LEAF_BYTES, bar1);
    }

    // --- stage x tile TRANSPOSED (feature-major, conflict-free gathers) ---
    {
        const int r  = warp * 32 + lane;
        const int gr = min(base + r, BATCH - 1);
        const float4* xg = reinterpret_cast<const float4*>(x + (size_t)gr * NFEAT);
        #pragma unroll 8
        for (int fq = 0; fq < NFEAT / 4; fq++) {
            float4 v = xg[fq];
            xs[(fq * 4 + 0) * TPB + r] = v.x;
            xs[(fq * 4 + 1) * TPB + r] = v.y;
            xs[(fq * 4 + 2) * TPB + r] = v.z;
            xs[(fq * 4 + 3) * TPB + r] = v.w;
        }
    }
    __syncthreads();

    float acc[NCLS];
    #pragma unroll
    for (int k = 0; k < NCLS; k++) acc[k] = 0.0f;

    const char* xbyte = reinterpret_cast<const char*>(xs) + tid * 4;

    uint32_t barCur = bar0, barNxt = bar1;
    uint32_t ndCur = nodeDst0, ndNxt = nodeDst1;
    uint32_t lfCur = leafDst0, lfNxt = leafDst1;
    const int2*  nodes0 = reinterpret_cast<const int2*>(smem_raw + NODE_OFF);
    const int2*  nodes1 = reinterpret_cast<const int2*>(smem_raw + NODE_OFF + NODE_BYTES);
    const float* leaf0  = reinterpret_cast<const float*>(smem_raw + LEAF_OFF(0));
    const float* leaf1  = reinterpret_cast<const float*>(smem_raw + LEAF_OFF(1));
    const int2*  nCur = nodes0; const int2*  nNxt = nodes1;
    const float* lCur = leaf0;  const float* lNxt = leaf1;
    int phCur = 0, phNxt = 0;

    for (int c = 0; c < NCHUNK; c++) {
        mbar_wait(barCur, phCur);
        phCur ^= 1;

        for (int sg = 0; sg < CHUNK_STAGES; sg++) {
            const int2* ntBase = nCur + sg * NCLS * NINT;

            int idx[NCLS];
            #pragma unroll
            for (int k = 0; k < NCLS; k++) idx[k] = 0;

            // Level-major batching: 10 independent LDS.64 + 10 LDS.32 in
            // flight per level -> MLP for the smem pipe.
            #pragma unroll
            for (int l = 0; l < TREE_DEPTH; l++) {
                int2 nd[NCLS];
                #pragma unroll
                for (int k = 0; k < NCLS; k++)
                    nd[k] = ntBase[k * NINT + idx[k]];

                float xv[NCLS];
                #pragma unroll
                for (int k = 0; k < NCLS; k++)
                    xv[k] = *reinterpret_cast<const float*>(xbyte + nd[k].x);

                #pragma unroll
                for (int k = 0; k < NCLS; k++)
                    idx[k] = 2 * idx[k] + 1 + (xv[k] > __int_as_float(nd[k].y));
            }

            #pragma unroll
            for (int k = 0; k < NCLS; k++)
                acc[k] += lCur[(sg * NCLS + k) * NLEAF + (idx[k] - NINT)];
        }

        __syncthreads();   // all warps done with this buffer before overwrite
        if (c + 2 < NCHUNK && tid == 0) {
            const int nc = c + 2;
            mbar_expect_tx(barCur, BUF_BYTES);
            bulk_g2s(ndCur, g_nodes_p   + (size_t)nc * NODE_I2S,   NODE_BYTES, barCur);
            bulk_g2s(lfCur, leaf_values + (size_t)nc * LEAF_WORDS, LEAF_BYTES, barCur);
        }

        // swap
        uint32_t tb = barCur; barCur = barNxt; barNxt = tb;
        uint32_t tn = ndCur;  ndCur  = ndNxt;  ndNxt  = tn;
        uint32_t tl = lfCur;  lfCur  = lfNxt;  lfNxt  = tl;
        const int2*  tnp = nCur; nCur = nNxt; nNxt = tnp;
        const float* tlp = lCur; lCur = lNxt; lNxt = tlp;
        int tph = phCur; phCur = phNxt; phNxt = tph;
    }

    // --- epilogue ---
    if (tid < rows) {
        const int sample = base + tid;
        #pragma unroll
        for (int k = 0; k < NCLS; k++) {
            out[(size_t)sample * NCLS + k] = __ldg(init_out + k) + LR * acc[k];
        }
    }
}

extern "C" void kernel_launch(void* const* d_in, const int* in_sizes, int n_in,
                              void* d_out, int out_size)
{
    (void)in_sizes; (void)n_in; (void)out_size;

    const float* x           = (const float*)d_in[0];
    const int*   features    = (const int*)  d_in[1];
    const float* thresholds  = (const float*)d_in[2];
    const float* leaf_values = (const float*)d_in[3];
    const float* init_out    = (const float*)d_in[4];
    float*       out         = (float*)d_out;

    static bool attr_set = false;
    if (!attr_set) {
        cudaFuncSetAttribute(gbt_forest_kernel,
                             cudaFuncAttributeMaxDynamicSharedMemorySize,
                             SMEM_TOTAL);
        attr_set = true;
    }

    prep_nodes_kernel<<<(NTREES * NINT + 255) / 256, 256>>>(features, thresholds);
    gbt_forest_kernel<<<GRID, TPB, SMEM_TOTAL>>>(x, leaf_values, init_out, out);
}

// round 7
// speedup vs baseline: 1.1423x; 1.1423x over previous
#include <cuda_runtime.h>
#include <cstdint>

// Problem constants
#define BATCH      32768
#define NFEAT      128
#define NTREES     4000
#define NINT       63
#define NLEAF      64
#define NCLS       10
#define TREE_DEPTH 6
#define LR         0.1f

// Tiling: one CTA per SM; 224 samples/CTA, but 448 threads (two threads per
// sample, each owning half the stages of every chunk) -> 14 warps of TLP.
#define SPC        224                        // samples per CTA
#define TPB        448                        // 14 warps
#define GRID       ((BATCH + SPC - 1) / SPC)  // 147 CTAs over 148 SMs

#define CHUNK_STAGES 4
#define CHUNK_TREES  (CHUNK_STAGES * NCLS)    // 40 trees per buffer
#define NCHUNK       (NTREES / CHUNK_TREES)   // 100

// Node storage (built once by prep kernel into device-global scratch):
//   A: levels 0..4  -> int2 { f*SPC*4 byte offset, thr bits }, 32 slots/tree
//   B: level 5      -> int4 { f*SPC*4, thr bits, leafL bits, leafR bits }, 32/tree
#define A_I2_CHUNK  (CHUNK_TREES * 32)        // 1280
#define B_I4_CHUNK  (CHUNK_TREES * 32)        // 1280
#define A_BYTES     (A_I2_CHUNK * 8)          // 10240
#define B_BYTES     (B_I4_CHUNK * 16)         // 20480
#define BUF_BYTES   (A_BYTES + B_BYTES)       // 30720

// x tile: FEATURE-MAJOR, xs[f * SPC + r]; 224 ≡ 0 (mod 32) -> gather bank = lane.
#define XS_BYTES    (NFEAT * SPC * 4)         // 114688
#define BUF_OFF(b)  (XS_BYTES + (b) * BUF_BYTES)
#define MBAR_OFF    (XS_BYTES + 2 * BUF_BYTES)
#define SMEM_TOTAL  (MBAR_OFF + 16)           // 176144

__device__ int2 g_nodesA[NTREES * 32];
__device__ int4 g_nodesB[NTREES * 32];

extern __shared__ char smem_raw[];

__device__ __forceinline__ uint32_t s2u(const void* p) {
    uint32_t a;
    asm("{ .reg .u64 t; cvta.to.shared.u64 t, %1; cvt.u32.u64 %0, t; }"
        : "=r"(a) : "l"(p));
    return a;
}

__device__ __forceinline__ void mbar_init(uint32_t bar, uint32_t cnt) {
    asm volatile("mbarrier.init.shared.b64 [%0], %1;" :: "r"(bar), "r"(cnt) : "memory");
}

__device__ __forceinline__ void mbar_expect_tx(uint32_t bar, uint32_t bytes) {
    asm volatile("mbarrier.arrive.expect_tx.shared.b64 _, [%0], %1;"
                 :: "r"(bar), "r"(bytes) : "memory");
}

__device__ __forceinline__ void mbar_wait(uint32_t bar, uint32_t parity) {
    uint32_t done;
    asm volatile(
        "{\n\t.reg .pred p;\n\t"
        "mbarrier.try_wait.parity.acquire.cta.shared::cta.b64 p, [%1], %2;\n\t"
        "selp.b32 %0, 1, 0, p;\n\t}"
        : "=r"(done) : "r"(bar), "r"(parity) : "memory");
    while (!done) {
        asm volatile(
            "{\n\t.reg .pred p;\n\t"
            "mbarrier.try_wait.parity.acquire.cta.shared::cta.b64 p, [%1], %2, 0x989680;\n\t"
            "selp.b32 %0, 1, 0, p;\n\t}"
            : "=r"(done) : "r"(bar), "r"(parity) : "memory");
    }
}

__device__ __forceinline__ void bulk_g2s(uint32_t dst, const void* src,
                                         uint32_t bytes, uint32_t bar) {
    asm volatile(
        "cp.async.bulk.shared::cluster.global.mbarrier::complete_tx::bytes "
        "[%0], [%1], %2, [%3];"
        :: "r"(dst), "l"(src), "r"(bytes), "r"(bar) : "memory");
}

// ---- one-time prep: prescaled offsets, level-5 nodes fused with leaf pair ----
__global__ void prep_nodes_kernel(const int* __restrict__ features,
                                  const float* __restrict__ thresholds,
                                  const float* __restrict__ leaf_values)
{
    int i = blockIdx.x * blockDim.x + threadIdx.x;
    if (i >= NTREES * NINT) return;
    int t = i / NINT;
    int n = i - t * NINT;
    int  foff = features[i] * (SPC * 4);
    int  thr  = __float_as_int(thresholds[i]);
    if (n < 31) {
        g_nodesA[t * 32 + n] = make_int2(foff, thr);
    } else {
        int m = n - 31;   // 0..31, level-5 node; children are leaves 2m, 2m+1
        g_nodesB[t * 32 + m] = make_int4(
            foff, thr,
            __float_as_int(leaf_values[t * NLEAF + 2 * m]),
            __float_as_int(leaf_values[t * NLEAF + 2 * m + 1]));
    }
}

__global__ void __launch_bounds__(TPB, 1)
gbt_forest_kernel(const float* __restrict__ x,
                  const float* __restrict__ init_out,
                  float*       __restrict__ out)
{
    float* xs = reinterpret_cast<float*>(smem_raw);
    uint64_t* mbar = reinterpret_cast<uint64_t*>(smem_raw + MBAR_OFF);

    const int tid  = threadIdx.x;
    const int half = tid >= SPC;          // 0: stages 0-1, 1: stages 2-3
    const int r    = tid - half * SPC;    // sample slot 0..223
    const int base = blockIdx.x * SPC;

    const uint32_t bar0 = s2u(&mbar[0]);
    const uint32_t bar1 = s2u(&mbar[1]);
    const uint32_t dst0 = s2u(smem_raw + BUF_OFF(0));
    const uint32_t dst1 = s2u(smem_raw + BUF_OFF(1));

    const int2* gA = g_nodesA;
    const int4* gB = g_nodesB;

    // --- init barriers + prefetch chunks 0,1 ---
    if (tid == 0) {
        mbar_init(bar0, 1);
        mbar_init(bar1, 1);
        asm volatile("fence.proxy.async.shared::cta;" ::: "memory");
        mbar_expect_tx(bar0, BUF_BYTES);
        bulk_g2s(dst0,           gA,               A_BYTES, bar0);
        bulk_g2s(dst0 + A_BYTES, gB,               B_BYTES, bar0);
        mbar_expect_tx(bar1, BUF_BYTES);
        bulk_g2s(dst1,           gA + A_I2_CHUNK,  A_BYTES, bar1);
        bulk_g2s(dst1 + A_BYTES, gB + B_I4_CHUNK,  B_BYTES, bar1);
    }

    // --- stage x tile transposed; each sample row split across its 2 threads ---
    {
        const int gr = min(base + r, BATCH - 1);
        const float4* xg = reinterpret_cast<const float4*>(x + (size_t)gr * NFEAT)
                         + half * 16;                    // half 0: f 0-63, half 1: f 64-127
        #pragma unroll
        for (int fq = 0; fq < 16; fq++) {
            float4 v = xg[fq];
            const int f = half * 64 + fq * 4;
            xs[(f + 0) * SPC + r] = v.x;
            xs[(f + 1) * SPC + r] = v.y;
            xs[(f + 2) * SPC + r] = v.z;
            xs[(f + 3) * SPC + r] = v.w;
        }
    }
    __syncthreads();

    float acc[NCLS];
    #pragma unroll
    for (int k = 0; k < NCLS; k++) acc[k] = 0.0f;

    const char* xbyte = reinterpret_cast<const char*>(xs) + r * 4;
    const int sgBase = half * 2;   // this thread's stage pair within each chunk

    uint32_t barCur = bar0, barNxt = bar1;
    uint32_t dstCur = dst0, dstNxt = dst1;
    const char* pCur = smem_raw + BUF_OFF(0);
    const char* pNxt = smem_raw + BUF_OFF(1);
    int phCur = 0, phNxt = 0;

    for (int c = 0; c < NCHUNK; c++) {
        mbar_wait(barCur, phCur);
        phCur ^= 1;

        const int2* Ab = reinterpret_cast<const int2*>(pCur);
        const int4* Bb = reinterpret_cast<const int4*>(pCur + A_BYTES);

        #pragma unroll
        for (int s = 0; s < 2; s++) {
            const int sg = sgBase + s;
            const int2* At = Ab + sg * NCLS * 32;
            const int4* Bt = Bb + sg * NCLS * 32;

            #pragma unroll
            for (int k = 0; k < NCLS; k++) {
                const int2* nt = At + k * 32;
                int idx = 0;
                #pragma unroll
                for (int l = 0; l < 5; l++) {
                    int2  nd = nt[idx];
                    float xv = *reinterpret_cast<const float*>(xbyte + nd.x);
                    idx = 2 * idx + 1 + (xv > __int_as_float(nd.y));
                }
                // level 5: node fused with its two leaf values
                int4  nb = Bt[k * 32 + (idx - 31)];
                float xv = *reinterpret_cast<const float*>(xbyte + nb.x);
                acc[k] += (xv > __int_as_float(nb.y))
                        ? __int_as_float(nb.w) : __int_as_float(nb.z);
            }
        }

        __syncthreads();   // all warps done with this buffer before overwrite
        if (c + 2 < NCHUNK && tid == 0) {
            const int nc = c + 2;
            mbar_expect_tx(barCur, BUF_BYTES);
            bulk_g2s(dstCur,           gA + (size_t)nc * A_I2_CHUNK, A_BYTES, barCur);
            bulk_g2s(dstCur + A_BYTES, gB + (size_t)nc * B_I4_CHUNK, B_BYTES, barCur);
        }

        uint32_t tb = barCur; barCur = barNxt; barNxt = tb;
        uint32_t td = dstCur; dstCur = dstNxt; dstNxt = td;
        const char* tp = pCur; pCur = pNxt; pNxt = tp;
        int tph = phCur; phCur = phNxt; phNxt = tph;
    }

    // --- cross-half reduction through smem (reuse buffer region) ---
    float* red = reinterpret_cast<float*>(smem_raw + XS_BYTES);
    // loop's final __syncthreads already ordered all buffer reads before here
    if (half == 1) {
        #pragma unroll
        for (int k = 0; k < NCLS; k++) red[r * NCLS + k] = acc[k];
    }
    __syncthreads();

    if (half == 0 && base + r < BATCH) {
        const int sample = base + r;
        #pragma unroll
        for (int k = 0; k < NCLS; k++) {
            out[(size_t)sample * NCLS + k] =
                __ldg(init_out + k) + LR * (acc[k] + red[r * NCLS + k]);
        }
    }
}

extern "C" void kernel_launch(void* const* d_in, const int* in_sizes, int n_in,
                              void* d_out, int out_size)
{
    (void)in_sizes; (void)n_in; (void)out_size;

    const float* x           = (const float*)d_in[0];
    const int*   features    = (const int*)  d_in[1];
    const float* thresholds  = (const float*)d_in[2];
    const float* leaf_values = (const float*)d_in[3];
    const float* init_out    = (const float*)d_in[4];
    float*       out         = (float*)d_out;

    static bool attr_set = false;
    if (!attr_set) {
        cudaFuncSetAttribute(gbt_forest_kernel,
                             cudaFuncAttributeMaxDynamicSharedMemorySize,
                             SMEM_TOTAL);
        attr_set = true;
    }

    prep_nodes_kernel<<<(NTREES * NINT + 255) / 256, 256>>>(features, thresholds,
                                                            leaf_values);
    gbt_forest_kernel<<<GRID, TPB, SMEM_TOTAL>>>(x, init_out, out);
}